// round 7
// baseline (speedup 1.0000x reference)
#include <cuda_runtime.h>
#include <math.h>
#include <stdint.h>

#define BB    128   // batch
#define TT    512   // timesteps
#define NNH   512   // hidden
#define NCOLT 16    // column tiles
#define NBT   8     // batch tiles
#define NCTA  128
#define NJ    32    // columns per CTA
#define MB    16    // batches per CTA
#define NTHR  512
#define WPf   516   // weight row pitch (floats)
#define CPf   516   // state row pitch (floats)
#define FPch  132   // fredb pitch

// -------- persistent device state --------
__device__ float g_c[2][NNH * BB];      // [n][b], double buffered
__device__ float g_h[2][NNH * BB];
__device__ unsigned int g_bar;

__global__ void hippo_init(const float* __restrict__ h0, const float* __restrict__ c0) {
    int idx = blockIdx.x * blockDim.x + threadIdx.x;
    if (idx == 0) g_bar = 0u;
    int total = NNH * BB;
    for (int i = idx; i < total; i += gridDim.x * blockDim.x) {
        int n = i / BB;
        int b = i % BB;
        g_c[0][i] = c0[b * NNH + n];
        g_h[0][i] = h0[b * NNH + n];
    }
}

__device__ __forceinline__ void bar_arrive() {
    __syncthreads();
    if (threadIdx.x == 0) {
        asm volatile("red.release.gpu.global.add.u32 [%0], 1;"
                     :: "l"(&g_bar) : "memory");
    }
}
__device__ __forceinline__ void bar_wait(unsigned int target) {
    if (threadIdx.x == 0) {
        unsigned int v;
        do {
            asm volatile("ld.acquire.gpu.global.u32 %0, [%1];"
                         : "=r"(v) : "l"(&g_bar) : "memory");
        } while (v < target);
    }
    __syncthreads();
}

__device__ __forceinline__ void fma2(uint64_t& d, uint64_t a, uint64_t b) {
    asm("fma.rn.f32x2 %0, %1, %2, %0;" : "+l"(d) : "l"(a), "l"(b));
}
__device__ __forceinline__ uint64_t pack2(float x, float y) {
    uint64_t r;
    asm("mov.b64 %0, {%1, %2};" : "=l"(r) : "f"(x), "f"(y));
    return r;
}
__device__ __forceinline__ float2 unpack2(uint64_t v) {
    float2 r;
    asm("mov.b64 {%0, %1}, %2;" : "=f"(r.x), "=f"(r.y) : "l"(v));
    return r;
}

// smem (floats): Wi[NJ*WPf] Wh[NJ*WPf] c[MB*CPf] h[MB*CPf] wf[512]
//                hs_tile[NJ*18] fredb[16*FPch] f_s[16] wx[NJ] bb[NJ]
#define SM_FLOATS (2 * NJ * WPf + 2 * MB * CPf + 512 + NJ * 18 + 16 * FPch + 16 + 2 * NJ)
#define SM_BYTES  (SM_FLOATS * 4)

__global__ __launch_bounds__(NTHR, 1) void hippo_persistent(
    const float* __restrict__ x,
    const float* __restrict__ Wi,
    const float* __restrict__ bi,
    const float* __restrict__ Wh,
    const float* __restrict__ bh,
    const float* __restrict__ Wf,
    const float* __restrict__ bfv,
    const float* __restrict__ A_stack,
    const float* __restrict__ B_stack,
    float* __restrict__ out)
{
    extern __shared__ float sm[];
    float* Wi_s  = sm;
    float* Wh_s  = Wi_s + NJ * WPf;
    float* c_s   = Wh_s + NJ * WPf;
    float* h_s   = c_s + MB * CPf;
    float* wf_s  = h_s + MB * CPf;      // 512
    float* hs_t  = wf_s + 512;          // NJ*18
    float* fredb = hs_t + NJ * 18;      // 16*FPch
    float* f_s   = fredb + 16 * FPch;   // 16
    float* wx_s  = f_s + 16;            // NJ
    float* bb_s  = wx_s + NJ;           // NJ

    const int cta   = blockIdx.x;
    const int ct    = cta & (NCOLT - 1);
    const int bt    = cta >> 4;
    const int jbase = ct * NJ;
    const int bbase = bt * MB;
    const int tid   = threadIdx.x;
    const int j     = tid >> 4;          // 0..31 column
    const int kh    = (tid >> 3) & 1;    // k-half
    const int bg    = tid & 7;           // 0..7
    const int b0    = bg;                // partial batches bg, bg+8
    const int b1    = bg + 8;
    const int myb   = bg + 8 * kh;       // this thread's final batch
    const int jg    = jbase + j;
    const int kbase = kh * 256;

    // ---- one-time loads ----
    for (int i = tid; i < NJ * NNH; i += NTHR) {
        int r = i >> 9, k = i & 511;
        Wi_s[r * WPf + k] = Wi[(jbase + r) * (NNH + 1) + 1 + k];
        Wh_s[r * WPf + k] = Wh[(jbase + r) * (NNH + 1) + 1 + k];
    }
    for (int i = tid; i < NNH; i += NTHR) wf_s[i] = Wf[1 + i];
    if (tid < NJ) {
        wx_s[tid] = Wi[(jbase + tid) * (NNH + 1)] + Wh[(jbase + tid) * (NNH + 1)];
        bb_s[tid] = bi[jbase + tid] + bh[jbase + tid];
    }
    // ---- initial state staging (k-major per batch) ----
    {
        const int q = tid & 3, n0 = tid >> 2;    // n0: 0..127
        #pragma unroll
        for (int it = 0; it < 4; ++it) {
            int n = n0 + 128 * it;
            float4 c4 = *(const float4*)(g_c[0] + n * BB + bbase + 4 * q);
            float4 h4 = *(const float4*)(g_h[0] + n * BB + bbase + 4 * q);
            c_s[(4 * q + 0) * CPf + n] = c4.x;  c_s[(4 * q + 1) * CPf + n] = c4.y;
            c_s[(4 * q + 2) * CPf + n] = c4.z;  c_s[(4 * q + 3) * CPf + n] = c4.w;
            h_s[(4 * q + 0) * CPf + n] = h4.x;  h_s[(4 * q + 1) * CPf + n] = h4.y;
            h_s[(4 * q + 2) * CPf + n] = h4.z;  h_s[(4 * q + 3) * CPf + n] = h4.w;
        }
    }
    __syncthreads();

    const float wf0 = Wf[0];
    const float bf0 = bfv[0];
    float* out_hs = out;
    float* out_cf = out + (size_t)BB * TT * NNH;

    const float* wiP = Wi_s + j * WPf + kbase;
    const float* whP = Wh_s + j * WPf + kbase;
    const float* cP0 = c_s + b0 * CPf + kbase;
    const float* cP1 = c_s + b1 * CPf + kbase;
    const float* hP0 = h_s + b0 * CPf + kbase;
    const float* hP1 = h_s + b1 * CPf + kbase;

    for (int t = 0; t < TT; ++t) {
        const int nxt = (t & 1) ^ 1;

        float xb = __ldcg(&x[(size_t)(bbase + myb) * TT + t]);

        // ===== main k-loop (half range): gates + P, k-pair FMA2 =====
        const float* Arow = A_stack + ((size_t)t * NNH + jg) * NNH + kbase;
        float4 ring[4];
        #pragma unroll
        for (int r = 0; r < 4; ++r)
            ring[r] = __ldg((const float4*)(Arow + 4 * r));

        uint64_t aI0 = 0, aI1 = 0, aH0 = 0, aH1 = 0, aP0 = 0, aP1 = 0;
        #pragma unroll 4
        for (int m = 0; m < 64; ++m) {
            const int k = 4 * m;
            float4 a4 = ring[m & 3];
            int kn = k + 16;
            if (kn >= 256) kn = 0;              // stay inside this half-row
            ring[m & 3] = __ldg((const float4*)(Arow + kn));

            ulonglong2 wi2 = *(const ulonglong2*)(wiP + k);
            ulonglong2 wh2 = *(const ulonglong2*)(whP + k);
            ulonglong2 cA  = *(const ulonglong2*)(cP0 + k);
            ulonglong2 cB  = *(const ulonglong2*)(cP1 + k);
            ulonglong2 hA  = *(const ulonglong2*)(hP0 + k);
            ulonglong2 hB  = *(const ulonglong2*)(hP1 + k);
            uint64_t aA = pack2(a4.x, a4.y);
            uint64_t aB = pack2(a4.z, a4.w);

            fma2(aI0, wi2.x, cA.x);  fma2(aI0, wi2.y, cA.y);
            fma2(aI1, wi2.x, cB.x);  fma2(aI1, wi2.y, cB.y);
            fma2(aH0, wh2.x, hA.x);  fma2(aH0, wh2.y, hA.y);
            fma2(aH1, wh2.x, hB.x);  fma2(aH1, wh2.y, hB.y);
            fma2(aP0, aA, cA.x);     fma2(aP0, aB, cA.y);
            fma2(aP1, aA, cB.x);     fma2(aP1, aB, cB.y);
        }

        // ===== cross-k-half reduction (partner = lane ^ 8) =====
        float2 i0 = unpack2(aI0), i1 = unpack2(aI1);
        float2 hh0 = unpack2(aH0), hh1 = unpack2(aH1);
        float gA = i0.x + i0.y + hh0.x + hh0.y;
        float gB = i1.x + i1.y + hh1.x + hh1.y;
        gA += __shfl_xor_sync(0xffffffffu, gA, 8);
        gB += __shfl_xor_sync(0xffffffffu, gB, 8);
        float2 pv0 = unpack2(aP0), pv1 = unpack2(aP1);
        float pA = pv0.x + pv0.y;
        float pB = pv1.x + pv1.y;
        pA += __shfl_xor_sync(0xffffffffu, pA, 8);
        pB += __shfl_xor_sync(0xffffffffu, pB, 8);

        float gate = (kh ? gB : gA) + bb_s[j] + wx_s[j] * xb;
        float p    = kh ? pB : pA;

        float o  = 1.f / (1.f + __expf(-gate));
        float hn = o * tanhf(c_s[myb * CPf + jg]);
        g_h[nxt][jg * BB + bbase + myb] = hn;
        hs_t[j * 18 + myb] = hn;

        bar_arrive();                                // #1: h_new visible

        // coalesced hs output (512 thr x 1 float = exact 32x16 tile)
        {
            int bo = tid >> 5;       // 0..15
            int jq = tid & 31;       // 0..31
            out_hs[(size_t)(bbase + bo) * TT * NNH + (size_t)t * NNH + jbase + jq]
                = hs_t[jq * 18 + bo];
        }
        bar_wait((unsigned)(2 * t + 1) * NCTA);

        // ===== f partials from full h (own batches) =====
        {
            const int q = tid & 3, n0 = tid >> 2;    // n0: 0..127
            float fp0 = 0.f, fp1 = 0.f, fp2 = 0.f, fp3 = 0.f;
            #pragma unroll
            for (int it = 0; it < 4; ++it) {
                int n = n0 + 128 * it;
                float4 h4 = __ldcg((const float4*)(g_h[nxt] + n * BB + bbase + 4 * q));
                float w = wf_s[n];
                fp0 += w * h4.x;  fp1 += w * h4.y;
                fp2 += w * h4.z;  fp3 += w * h4.w;
            }
            fredb[(4 * q + 0) * FPch + n0] = fp0;
            fredb[(4 * q + 1) * FPch + n0] = fp1;
            fredb[(4 * q + 2) * FPch + n0] = fp2;
            fredb[(4 * q + 3) * FPch + n0] = fp3;
        }
        __syncthreads();
        if (tid < MB) {
            float s = 0.f;
            #pragma unroll
            for (int g4 = 0; g4 < 32; ++g4) {
                float4 v = *(const float4*)(fredb + tid * FPch + 4 * g4);
                s += v.x + v.y + v.z + v.w;
            }
            f_s[tid] = bf0 + wf0 * __ldcg(&x[(size_t)(bbase + tid) * TT + t]) + s;
        }
        __syncthreads();

        // ===== c_new =====
        {
            float Bt = __ldg(&B_stack[t * NNH + jg]);
            float cn = p + f_s[myb] * Bt;
            g_c[nxt][jg * BB + bbase + myb] = cn;
            if (t == TT - 1)
                out_cf[(size_t)(bbase + myb) * NNH + jg] = cn;
        }
        bar_arrive();                                // #2: c_new visible
        bar_wait((unsigned)(2 * t + 2) * NCTA);

        // ===== stage c,h (k-major transpose) for next step =====
        {
            const int q = tid & 3, n0 = tid >> 2;
            #pragma unroll
            for (int it = 0; it < 4; ++it) {
                int n = n0 + 128 * it;
                float4 c4 = __ldcg((const float4*)(g_c[nxt] + n * BB + bbase + 4 * q));
                float4 h4 = __ldcg((const float4*)(g_h[nxt] + n * BB + bbase + 4 * q));
                c_s[(4 * q + 0) * CPf + n] = c4.x;  c_s[(4 * q + 1) * CPf + n] = c4.y;
                c_s[(4 * q + 2) * CPf + n] = c4.z;  c_s[(4 * q + 3) * CPf + n] = c4.w;
                h_s[(4 * q + 0) * CPf + n] = h4.x;  h_s[(4 * q + 1) * CPf + n] = h4.y;
                h_s[(4 * q + 2) * CPf + n] = h4.z;  h_s[(4 * q + 3) * CPf + n] = h4.w;
            }
        }
        __syncthreads();
    }
}

extern "C" void kernel_launch(void* const* d_in, const int* in_sizes, int n_in,
                              void* d_out, int out_size) {
    const float* x   = (const float*)d_in[0];
    const float* h0  = (const float*)d_in[1];
    const float* c0  = (const float*)d_in[2];
    const float* Wi  = (const float*)d_in[3];
    const float* bi  = (const float*)d_in[4];
    const float* Wh  = (const float*)d_in[5];
    const float* bh  = (const float*)d_in[6];
    const float* Wf  = (const float*)d_in[7];
    const float* bf  = (const float*)d_in[8];
    const float* A_s = (const float*)d_in[9];
    const float* B_s = (const float*)d_in[10];
    float* out = (float*)d_out;

    cudaFuncSetAttribute(hippo_persistent,
                         cudaFuncAttributeMaxDynamicSharedMemorySize, SM_BYTES);
    hippo_init<<<128, 256>>>(h0, c0);
    hippo_persistent<<<NCTA, NTHR, SM_BYTES>>>(x, Wi, bi, Wh, bh, Wf, bf,
                                               A_s, B_s, out);
}

// round 8
// speedup vs baseline: 1.4910x; 1.4910x over previous
#include <cuda_runtime.h>
#include <math.h>
#include <stdint.h>

#define BB    128
#define TT    512
#define NNH   512
#define NCOLT 16
#define NCTA  128
#define NJ    32     // columns per CTA
#define MB    16     // batches per CTA
#define NTHR  512
#define WP    516    // weight row pitch (floats)
#define CP    516    // state row pitch (floats)
#define RP    20     // reduction buffer pitch

// -------- persistent device state --------
__device__ float g_c[2][NNH * BB];      // [n][b], double buffered
__device__ float g_h[2][NNH * BB];
__device__ float g_fpart[NCOLT * BB];
__device__ unsigned int g_bar;

__global__ void hippo_init(const float* __restrict__ h0, const float* __restrict__ c0) {
    int idx = blockIdx.x * blockDim.x + threadIdx.x;
    if (idx == 0) g_bar = 0u;
    int total = NNH * BB;
    for (int i = idx; i < total; i += gridDim.x * blockDim.x) {
        int n = i / BB;
        int b = i % BB;
        g_c[0][i] = c0[b * NNH + n];
        g_h[0][i] = h0[b * NNH + n];
    }
}

__device__ __forceinline__ void bar_arrive() {
    __syncthreads();
    if (threadIdx.x == 0) {
        asm volatile("red.release.gpu.global.add.u32 [%0], 1;"
                     :: "l"(&g_bar) : "memory");
    }
}
__device__ __forceinline__ void bar_wait(unsigned int target) {
    if (threadIdx.x == 0) {
        unsigned int v;
        do {
            asm volatile("ld.acquire.gpu.global.u32 %0, [%1];"
                         : "=r"(v) : "l"(&g_bar) : "memory");
        } while (v < target);
    }
    __syncthreads();
}

__device__ __forceinline__ void fma2(uint64_t& d, uint64_t a, uint64_t b) {
    asm("fma.rn.f32x2 %0, %1, %2, %0;" : "+l"(d) : "l"(a), "l"(b));
}
__device__ __forceinline__ float2 unpack2(uint64_t v) {
    float2 r;
    asm("mov.b64 {%0, %1}, %2;" : "=f"(r.x), "=f"(r.y) : "l"(v));
    return r;
}

// smem floats layout
#define SM_FLOATS (2 * NJ * WP + 2 * MB * CP + 256 * RP + 512 + 32 * 17 + 16 * 36 + 16 + 16 + 32 + 32)
#define SM_BYTES  (SM_FLOATS * 4)

__global__ __launch_bounds__(NTHR, 1) void hippo_persistent(
    const float* __restrict__ x,
    const float* __restrict__ Wi,
    const float* __restrict__ bi,
    const float* __restrict__ Wh,
    const float* __restrict__ bh,
    const float* __restrict__ Wf,
    const float* __restrict__ bfv,
    const float* __restrict__ A_stack,
    const float* __restrict__ B_stack,
    float* __restrict__ out)
{
    extern __shared__ float sm[];
    float* Wi_s = sm;                       // NJ*WP
    float* Wh_s = Wi_s + NJ * WP;           // NJ*WP
    float* cS   = Wh_s + NJ * WP;           // MB*CP   (rows=b, cols=global k)
    float* hS   = cS + MB * CP;             // MB*CP
    float* red  = hS + MB * CP;             // 256*RP
    float* wf_s = red + 256 * RP;           // 512
    float* hs_t = wf_s + 512;               // 32*17
    float* fred = hs_t + 32 * 17;           // 16*36 (rows=b)
    float* xs   = fred + 16 * 36;           // 16
    float* f_s  = xs + 16;                  // 16
    float* wx_s = f_s + 16;                 // 32
    float* bb_s = wx_s + 32;                // 32

    const int cta   = blockIdx.x;
    const int ct    = cta & (NCOLT - 1);
    const int bt_t  = cta >> 4;
    const int jbase = ct * NJ;
    const int bbase = bt_t * MB;
    const int tid   = threadIdx.x;

    const int kc   = tid >> 5;              // 0..15 k-chunk
    const int lane = tid & 31;
    const int jt   = lane >> 2;             // 0..7
    const int bt   = lane & 3;              // 0..3
    const int kb   = kc * 32;

    const int j_own = tid >> 4;             // 0..31 (owner cell)
    const int b_own = tid & 15;

    // ---- one-time loads ----
    for (int i = tid; i < NJ * NNH; i += NTHR) {
        int r = i >> 9, k = i & 511;
        Wi_s[r * WP + k] = Wi[(jbase + r) * (NNH + 1) + 1 + k];
        Wh_s[r * WP + k] = Wh[(jbase + r) * (NNH + 1) + 1 + k];
    }
    for (int i = tid; i < NNH; i += NTHR) wf_s[i] = Wf[1 + i];
    if (tid < NJ) {
        wx_s[tid] = Wi[(jbase + tid) * (NNH + 1)] + Wh[(jbase + tid) * (NNH + 1)];
        bb_s[tid] = bi[jbase + tid] + bh[jbase + tid];
    }
    // ---- initial state staging (rows=b, cols=k) ----
    {
        const int q = tid & 3, n0 = tid >> 2;   // n0 0..127
        #pragma unroll
        for (int it = 0; it < 4; ++it) {
            int n = n0 + 128 * it;
            float4 c4 = *(const float4*)(g_c[0] + n * BB + bbase + 4 * q);
            float4 h4 = *(const float4*)(g_h[0] + n * BB + bbase + 4 * q);
            cS[(4 * q + 0) * CP + n] = c4.x;  cS[(4 * q + 1) * CP + n] = c4.y;
            cS[(4 * q + 2) * CP + n] = c4.z;  cS[(4 * q + 3) * CP + n] = c4.w;
            hS[(4 * q + 0) * CP + n] = h4.x;  hS[(4 * q + 1) * CP + n] = h4.y;
            hS[(4 * q + 2) * CP + n] = h4.z;  hS[(4 * q + 3) * CP + n] = h4.w;
        }
    }
    __syncthreads();

    const float wf0 = Wf[0];
    const float bf0 = bfv[0];
    float* out_hs = out;
    float* out_cf = out + (size_t)BB * TT * NNH;

    // per-thread base pointers for the main passes
    const float* wiB[4];
    const float* whB[4];
    const float* cB[4];
    const float* hB[4];
    #pragma unroll
    for (int jj = 0; jj < 4; ++jj) {
        wiB[jj] = Wi_s + (jt + 8 * jj) * WP + kb;
        whB[jj] = Wh_s + (jt + 8 * jj) * WP + kb;
    }
    #pragma unroll
    for (int bb = 0; bb < 4; ++bb) {
        cB[bb] = cS + (bt + 4 * bb) * CP + kb;
        hB[bb] = hS + (bt + 4 * bb) * CP + kb;
    }

    for (int t = 0; t < TT; ++t) {
        const int nxt = (t & 1) ^ 1;

        if (tid < MB) xs[tid] = __ldcg(&x[(size_t)(bbase + tid) * TT + t]);

        // ================= PASS 1: gates (Wi·c + Wh·h), 4j x 4b tile =================
        uint64_t acc[4][4];
        #pragma unroll
        for (int jj = 0; jj < 4; ++jj)
            #pragma unroll
            for (int bb = 0; bb < 4; ++bb) acc[jj][bb] = 0;

        #pragma unroll
        for (int m = 0; m < 8; ++m) {
            const int ko = 4 * m;
            ulonglong2 wiv[4], whv[4], cv[4], hv[4];
            #pragma unroll
            for (int jj = 0; jj < 4; ++jj) {
                wiv[jj] = *(const ulonglong2*)(wiB[jj] + ko);
                whv[jj] = *(const ulonglong2*)(whB[jj] + ko);
            }
            #pragma unroll
            for (int bb = 0; bb < 4; ++bb) {
                cv[bb] = *(const ulonglong2*)(cB[bb] + ko);
                hv[bb] = *(const ulonglong2*)(hB[bb] + ko);
            }
            #pragma unroll
            for (int jj = 0; jj < 4; ++jj)
                #pragma unroll
                for (int bb = 0; bb < 4; ++bb) {
                    fma2(acc[jj][bb], wiv[jj].x, cv[bb].x);
                    fma2(acc[jj][bb], wiv[jj].y, cv[bb].y);
                    fma2(acc[jj][bb], whv[jj].x, hv[bb].x);
                    fma2(acc[jj][bb], whv[jj].y, hv[bb].y);
                }
        }

        // ====== gate reduction over 16 k-chunks (2 phases, 20KB buffer) ======
        float gsum = 0.f;
        #pragma unroll
        for (int jj = 0; jj < 2; ++jj)
            #pragma unroll
            for (int bb = 0; bb < 4; ++bb) {
                float2 v = unpack2(acc[jj][bb]);
                red[((jt + 8 * jj) * 16 + (bt + 4 * bb)) * RP + kc] = v.x + v.y;
            }
        __syncthreads();
        if (tid < 256) {
            const float* rp = red + tid * RP;
            float4 r0 = *(const float4*)(rp + 0);
            float4 r1 = *(const float4*)(rp + 4);
            float4 r2 = *(const float4*)(rp + 8);
            float4 r3 = *(const float4*)(rp + 12);
            gsum = (r0.x + r0.y + r0.z + r0.w) + (r1.x + r1.y + r1.z + r1.w)
                 + (r2.x + r2.y + r2.z + r2.w) + (r3.x + r3.y + r3.z + r3.w);
        }
        __syncthreads();
        #pragma unroll
        for (int jj = 2; jj < 4; ++jj)
            #pragma unroll
            for (int bb = 0; bb < 4; ++bb) {
                float2 v = unpack2(acc[jj][bb]);
                red[((jt + 8 * (jj - 2)) * 16 + (bt + 4 * bb)) * RP + kc] = v.x + v.y;
            }
        __syncthreads();
        if (tid >= 256) {
            const float* rp = red + (tid - 256) * RP;
            float4 r0 = *(const float4*)(rp + 0);
            float4 r1 = *(const float4*)(rp + 4);
            float4 r2 = *(const float4*)(rp + 8);
            float4 r3 = *(const float4*)(rp + 12);
            gsum = (r0.x + r0.y + r0.z + r0.w) + (r1.x + r1.y + r1.z + r1.w)
                 + (r2.x + r2.y + r2.z + r2.w) + (r3.x + r3.y + r3.z + r3.w);
        }

        // ====== h_new (each thread owns cell (j_own, b_own)) ======
        {
            float gate = gsum + bb_s[j_own] + wx_s[j_own] * xs[b_own];
            float o  = 1.f / (1.f + __expf(-gate));
            float hn = o * tanhf(cS[b_own * CP + jbase + j_own]);
            g_h[nxt][(jbase + j_own) * BB + bbase + b_own] = hn;
            hs_t[j_own * 17 + b_own] = hn;
            fred[b_own * 36 + j_own] = wf_s[jbase + j_own] * hn;
        }
        __syncthreads();
        if (tid < MB) {
            float s = 0.f;
            #pragma unroll
            for (int g4 = 0; g4 < 8; ++g4) {
                float4 v = *(const float4*)(fred + tid * 36 + 4 * g4);
                s += v.x + v.y + v.z + v.w;
            }
            g_fpart[ct * BB + bbase + tid] = s;
        }
        // coalesced hs store
        {
            int bo = tid >> 5, jq = tid & 31;
            out_hs[(size_t)(bbase + bo) * TT * NNH + (size_t)t * NNH + jbase + jq]
                = hs_t[jq * 17 + bo];
        }
        bar_arrive();                             // #1: h_new + f partials visible

        // ================= PASS 2: P = A_t · c  (hides barrier #1) =================
        uint64_t pacc[4][4];
        #pragma unroll
        for (int jj = 0; jj < 4; ++jj)
            #pragma unroll
            for (int bb = 0; bb < 4; ++bb) pacc[jj][bb] = 0;

        const float* Ar[4];
        #pragma unroll
        for (int jj = 0; jj < 4; ++jj)
            Ar[jj] = A_stack + ((size_t)t * NNH + (jbase + jt + 8 * jj)) * NNH + kb;

        float4 aC[4], aN[4];
        #pragma unroll
        for (int jj = 0; jj < 4; ++jj)
            aC[jj] = __ldg((const float4*)(Ar[jj]));

        #pragma unroll
        for (int m = 0; m < 8; ++m) {
            if (m < 7) {
                #pragma unroll
                for (int jj = 0; jj < 4; ++jj)
                    aN[jj] = __ldg((const float4*)(Ar[jj] + 4 * (m + 1)));
            }
            ulonglong2 cv[4];
            #pragma unroll
            for (int bb = 0; bb < 4; ++bb)
                cv[bb] = *(const ulonglong2*)(cB[bb] + 4 * m);
            #pragma unroll
            for (int jj = 0; jj < 4; ++jj) {
                ulonglong2 av = *(const ulonglong2*)(&aC[jj]);
                #pragma unroll
                for (int bb = 0; bb < 4; ++bb) {
                    fma2(pacc[jj][bb], av.x, cv[bb].x);
                    fma2(pacc[jj][bb], av.y, cv[bb].y);
                }
            }
            if (m < 7) {
                #pragma unroll
                for (int jj = 0; jj < 4; ++jj) aC[jj] = aN[jj];
            }
        }

        // ====== P reduction (2 phases, reuse buffer) ======
        float psum = 0.f;
        #pragma unroll
        for (int jj = 0; jj < 2; ++jj)
            #pragma unroll
            for (int bb = 0; bb < 4; ++bb) {
                float2 v = unpack2(pacc[jj][bb]);
                red[((jt + 8 * jj) * 16 + (bt + 4 * bb)) * RP + kc] = v.x + v.y;
            }
        __syncthreads();
        if (tid < 256) {
            const float* rp = red + tid * RP;
            float4 r0 = *(const float4*)(rp + 0);
            float4 r1 = *(const float4*)(rp + 4);
            float4 r2 = *(const float4*)(rp + 8);
            float4 r3 = *(const float4*)(rp + 12);
            psum = (r0.x + r0.y + r0.z + r0.w) + (r1.x + r1.y + r1.z + r1.w)
                 + (r2.x + r2.y + r2.z + r2.w) + (r3.x + r3.y + r3.z + r3.w);
        }
        __syncthreads();
        #pragma unroll
        for (int jj = 2; jj < 4; ++jj)
            #pragma unroll
            for (int bb = 0; bb < 4; ++bb) {
                float2 v = unpack2(pacc[jj][bb]);
                red[((jt + 8 * (jj - 2)) * 16 + (bt + 4 * bb)) * RP + kc] = v.x + v.y;
            }
        __syncthreads();
        if (tid >= 256) {
            const float* rp = red + (tid - 256) * RP;
            float4 r0 = *(const float4*)(rp + 0);
            float4 r1 = *(const float4*)(rp + 4);
            float4 r2 = *(const float4*)(rp + 8);
            float4 r3 = *(const float4*)(rp + 12);
            psum = (r0.x + r0.y + r0.z + r0.w) + (r1.x + r1.y + r1.z + r1.w)
                 + (r2.x + r2.y + r2.z + r2.w) + (r3.x + r3.y + r3.z + r3.w);
        }

        bar_wait((unsigned)(2 * t + 1) * NCTA);   // all h_new + f partials visible

        // stage hS for next step (h is final now)
        {
            const int q = tid & 3, n0 = tid >> 2;
            #pragma unroll
            for (int it = 0; it < 4; ++it) {
                int n = n0 + 128 * it;
                float4 h4 = __ldcg((const float4*)(g_h[nxt] + n * BB + bbase + 4 * q));
                hS[(4 * q + 0) * CP + n] = h4.x;  hS[(4 * q + 1) * CP + n] = h4.y;
                hS[(4 * q + 2) * CP + n] = h4.z;  hS[(4 * q + 3) * CP + n] = h4.w;
            }
        }
        if (tid < MB) {
            float s = 0.f;
            #pragma unroll
            for (int q = 0; q < NCOLT; ++q)
                s += __ldcg(&g_fpart[q * BB + bbase + tid]);
            f_s[tid] = bf0 + wf0 * xs[tid] + s;
        }
        __syncthreads();

        // ====== c_new ======
        {
            float Bt = __ldg(&B_stack[t * NNH + jbase + j_own]);
            float cn = psum + f_s[b_own] * Bt;
            g_c[nxt][(jbase + j_own) * BB + bbase + b_own] = cn;
            if (t == TT - 1)
                out_cf[(size_t)(bbase + b_own) * NNH + jbase + j_own] = cn;
        }
        bar_arrive();                             // #2
        bar_wait((unsigned)(2 * t + 2) * NCTA);   // all c_new visible

        // stage cS for next step
        {
            const int q = tid & 3, n0 = tid >> 2;
            #pragma unroll
            for (int it = 0; it < 4; ++it) {
                int n = n0 + 128 * it;
                float4 c4 = __ldcg((const float4*)(g_c[nxt] + n * BB + bbase + 4 * q));
                cS[(4 * q + 0) * CP + n] = c4.x;  cS[(4 * q + 1) * CP + n] = c4.y;
                cS[(4 * q + 2) * CP + n] = c4.z;  cS[(4 * q + 3) * CP + n] = c4.w;
            }
        }
        __syncthreads();
    }
}

extern "C" void kernel_launch(void* const* d_in, const int* in_sizes, int n_in,
                              void* d_out, int out_size) {
    const float* x   = (const float*)d_in[0];
    const float* h0  = (const float*)d_in[1];
    const float* c0  = (const float*)d_in[2];
    const float* Wi  = (const float*)d_in[3];
    const float* bi  = (const float*)d_in[4];
    const float* Wh  = (const float*)d_in[5];
    const float* bh  = (const float*)d_in[6];
    const float* Wf  = (const float*)d_in[7];
    const float* bf  = (const float*)d_in[8];
    const float* A_s = (const float*)d_in[9];
    const float* B_s = (const float*)d_in[10];
    float* out = (float*)d_out;

    cudaFuncSetAttribute(hippo_persistent,
                         cudaFuncAttributeMaxDynamicSharedMemorySize, SM_BYTES);
    hippo_init<<<128, 256>>>(h0, c0);
    hippo_persistent<<<NCTA, NTHR, SM_BYTES>>>(x, Wi, bi, Wh, bh, Wf, bf,
                                               A_s, B_s, out);
}

// round 9
// speedup vs baseline: 1.6081x; 1.0785x over previous
#include <cuda_runtime.h>
#include <math.h>
#include <stdint.h>

#define BB    128
#define TT    512
#define NNH   512
#define NCOLT 16
#define NGRP  8      // batch-tile groups (independent recurrences)
#define NCTA  128
#define NJ    32     // columns per CTA
#define MB    16     // batches per CTA
#define NTHR  512
#define WP    516    // weight row pitch (floats)
#define CP    516    // state row pitch (floats)
#define RP    20     // reduction buffer pitch

// -------- persistent device state (b-major: [b][n]) --------
__device__ float g_c[2][BB * NNH];
__device__ float g_h[2][BB * NNH];
__device__ float g_fpart[NCOLT * BB];
__device__ unsigned int g_bars[NGRP * 32];   // one counter per group, 128B apart

__global__ void hippo_init(const float* __restrict__ h0, const float* __restrict__ c0) {
    int idx = blockIdx.x * blockDim.x + threadIdx.x;
    if (idx < NGRP * 32) g_bars[idx] = 0u;
    int total = BB * NNH;
    for (int i = idx; i < total; i += gridDim.x * blockDim.x) {
        g_c[0][i] = c0[i];       // inputs are already (B,N) b-major
        g_h[0][i] = h0[i];
    }
}

__device__ __forceinline__ void grp_arrive(unsigned int* barp) {
    __syncthreads();
    if (threadIdx.x == 0) {
        asm volatile("red.release.gpu.global.add.u32 [%0], 1;"
                     :: "l"(barp) : "memory");
    }
}
__device__ __forceinline__ void grp_wait(unsigned int* barp, unsigned int target) {
    if (threadIdx.x == 0) {
        unsigned int v;
        do {
            asm volatile("ld.acquire.gpu.global.u32 %0, [%1];"
                         : "=r"(v) : "l"(barp) : "memory");
        } while (v < target);
    }
    __syncthreads();
}

__device__ __forceinline__ void fma2(uint64_t& d, uint64_t a, uint64_t b) {
    asm("fma.rn.f32x2 %0, %1, %2, %0;" : "+l"(d) : "l"(a), "l"(b));
}
__device__ __forceinline__ float2 unpack2(uint64_t v) {
    float2 r;
    asm("mov.b64 {%0, %1}, %2;" : "=f"(r.x), "=f"(r.y) : "l"(v));
    return r;
}
__device__ __forceinline__ void cpa16(float* dst, const float* src) {
    uint32_t d;
    asm("{ .reg .u64 t; cvta.to.shared.u64 t, %1; cvt.u32.u64 %0, t; }"
        : "=r"(d) : "l"(dst));
    asm volatile("cp.async.cg.shared.global [%0], [%1], 16;"
                 :: "r"(d), "l"(src) : "memory");
}
__device__ __forceinline__ void cpa_commit() {
    asm volatile("cp.async.commit_group;" ::: "memory");
}
__device__ __forceinline__ void cpa_wait_all() {
    asm volatile("cp.async.wait_group 0;" ::: "memory");
}

// smem floats
#define SM_FLOATS (2 * NJ * WP + 2 * MB * CP + 256 * RP + 512 + 32 * 17 + 16 * 36 + 16 + 16 + 32 + 32)
#define SM_BYTES  (SM_FLOATS * 4)

__global__ __launch_bounds__(NTHR, 1) void hippo_persistent(
    const float* __restrict__ x,
    const float* __restrict__ Wi,
    const float* __restrict__ bi,
    const float* __restrict__ Wh,
    const float* __restrict__ bh,
    const float* __restrict__ Wf,
    const float* __restrict__ bfv,
    const float* __restrict__ A_stack,
    const float* __restrict__ B_stack,
    float* __restrict__ out)
{
    extern __shared__ float sm[];
    float* Wi_s = sm;                       // NJ*WP
    float* Wh_s = Wi_s + NJ * WP;           // NJ*WP
    float* cS   = Wh_s + NJ * WP;           // MB*CP  rows=b, cols=k
    float* hS   = cS + MB * CP;             // MB*CP
    float* red  = hS + MB * CP;             // 256*RP
    float* wf_s = red + 256 * RP;           // 512
    float* tile = wf_s + 512;               // 32*17 (h then c transpose tile)
    float* fred = tile + 32 * 17;           // 16*36
    float* xs   = fred + 16 * 36;           // 16
    float* f_s  = xs + 16;                  // 16
    float* wx_s = f_s + 16;                 // 32
    float* bb_s = wx_s + 32;                // 32

    const int cta   = blockIdx.x;
    const int ct    = cta & (NCOLT - 1);
    const int grp   = cta >> 4;             // batch-tile group 0..7
    const int jbase = ct * NJ;
    const int bbase = grp * MB;
    const int tid   = threadIdx.x;

    const int kc   = tid >> 5;              // 0..15 k-chunk (warp-uniform)
    const int lane = tid & 31;
    const int jt   = lane >> 2;             // 0..7
    const int bt   = lane & 3;              // 0..3
    const int kb   = kc * 32;

    const int j_own = tid >> 4;             // 0..31
    const int b_own = tid & 15;

    unsigned int* barp = &g_bars[grp * 32];

    // ---- one-time loads ----
    for (int i = tid; i < NJ * NNH; i += NTHR) {
        int r = i >> 9, k = i & 511;
        Wi_s[r * WP + k] = Wi[(jbase + r) * (NNH + 1) + 1 + k];
        Wh_s[r * WP + k] = Wh[(jbase + r) * (NNH + 1) + 1 + k];
    }
    for (int i = tid; i < NNH; i += NTHR) wf_s[i] = Wf[1 + i];
    if (tid < NJ) {
        wx_s[tid] = Wi[(jbase + tid) * (NNH + 1)] + Wh[(jbase + tid) * (NNH + 1)];
        bb_s[tid] = bi[jbase + tid] + bh[jbase + tid];
    }
    // ---- initial state staging (b-major copy, no transpose) ----
    #pragma unroll
    for (int it = 0; it < 4; ++it) {
        int idx = tid + 512 * it;           // 0..2047 float4s
        int b = idx >> 7, kq = idx & 127;
        *(float4*)(cS + b * CP + 4 * kq) =
            *(const float4*)(g_c[0] + (size_t)(bbase + b) * NNH + 4 * kq);
        *(float4*)(hS + b * CP + 4 * kq) =
            *(const float4*)(g_h[0] + (size_t)(bbase + b) * NNH + 4 * kq);
    }
    __syncthreads();

    const float wf0 = Wf[0];
    const float bf0 = bfv[0];
    float* out_hs = out;
    float* out_cf = out + (size_t)BB * TT * NNH;

    const float* wiB[4];
    const float* whB[4];
    const float* cB[4];
    const float* hB[4];
    #pragma unroll
    for (int jj = 0; jj < 4; ++jj) {
        wiB[jj] = Wi_s + (jt + 8 * jj) * WP + kb;
        whB[jj] = Wh_s + (jt + 8 * jj) * WP + kb;
    }
    #pragma unroll
    for (int bb = 0; bb < 4; ++bb) {
        cB[bb] = cS + (bt + 4 * bb) * CP + kb;
        hB[bb] = hS + (bt + 4 * bb) * CP + kb;
    }

    for (int t = 0; t < TT; ++t) {
        const int nxt = (t & 1) ^ 1;

        if (tid < MB) xs[tid] = __ldcg(&x[(size_t)(bbase + tid) * TT + t]);

        // ================= PASS 1: gates (Wi·c + Wh·h) =================
        uint64_t acc[4][4];
        #pragma unroll
        for (int jj = 0; jj < 4; ++jj)
            #pragma unroll
            for (int bb = 0; bb < 4; ++bb) acc[jj][bb] = 0;

        #pragma unroll
        for (int m = 0; m < 8; ++m) {
            const int ko = 4 * m;
            ulonglong2 wiv[4], whv[4], cv[4], hv[4];
            #pragma unroll
            for (int jj = 0; jj < 4; ++jj) {
                wiv[jj] = *(const ulonglong2*)(wiB[jj] + ko);
                whv[jj] = *(const ulonglong2*)(whB[jj] + ko);
            }
            #pragma unroll
            for (int bb = 0; bb < 4; ++bb) {
                cv[bb] = *(const ulonglong2*)(cB[bb] + ko);
                hv[bb] = *(const ulonglong2*)(hB[bb] + ko);
            }
            #pragma unroll
            for (int jj = 0; jj < 4; ++jj)
                #pragma unroll
                for (int bb = 0; bb < 4; ++bb) {
                    fma2(acc[jj][bb], wiv[jj].x, cv[bb].x);
                    fma2(acc[jj][bb], wiv[jj].y, cv[bb].y);
                    fma2(acc[jj][bb], whv[jj].x, hv[bb].x);
                    fma2(acc[jj][bb], whv[jj].y, hv[bb].y);
                }
        }

        // A-prefetch for pass 2 (overlaps gate reduction)
        const float* Ar[4];
        float4 aC[4];
        #pragma unroll
        for (int jj = 0; jj < 4; ++jj) {
            Ar[jj] = A_stack + ((size_t)t * NNH + (jbase + jt + 8 * jj)) * NNH + kb;
            aC[jj] = __ldg((const float4*)(Ar[jj]));
        }

        // ====== gate reduction over 16 k-chunks (2 phases) ======
        float gsum = 0.f;
        #pragma unroll
        for (int jj = 0; jj < 2; ++jj)
            #pragma unroll
            for (int bb = 0; bb < 4; ++bb) {
                float2 v = unpack2(acc[jj][bb]);
                red[((jt + 8 * jj) * 16 + (bt + 4 * bb)) * RP + kc] = v.x + v.y;
            }
        __syncthreads();
        if (tid < 256) {
            const float* rp = red + tid * RP;
            float4 r0 = *(const float4*)(rp + 0);
            float4 r1 = *(const float4*)(rp + 4);
            float4 r2 = *(const float4*)(rp + 8);
            float4 r3 = *(const float4*)(rp + 12);
            gsum = (r0.x + r0.y + r0.z + r0.w) + (r1.x + r1.y + r1.z + r1.w)
                 + (r2.x + r2.y + r2.z + r2.w) + (r3.x + r3.y + r3.z + r3.w);
        }
        __syncthreads();
        #pragma unroll
        for (int jj = 2; jj < 4; ++jj)
            #pragma unroll
            for (int bb = 0; bb < 4; ++bb) {
                float2 v = unpack2(acc[jj][bb]);
                red[((jt + 8 * (jj - 2)) * 16 + (bt + 4 * bb)) * RP + kc] = v.x + v.y;
            }
        __syncthreads();
        if (tid >= 256) {
            const float* rp = red + (tid - 256) * RP;
            float4 r0 = *(const float4*)(rp + 0);
            float4 r1 = *(const float4*)(rp + 4);
            float4 r2 = *(const float4*)(rp + 8);
            float4 r3 = *(const float4*)(rp + 12);
            gsum = (r0.x + r0.y + r0.z + r0.w) + (r1.x + r1.y + r1.z + r1.w)
                 + (r2.x + r2.y + r2.z + r2.w) + (r3.x + r3.y + r3.z + r3.w);
        }

        // ====== h_new ======
        {
            float gate = gsum + bb_s[j_own] + wx_s[j_own] * xs[b_own];
            float o  = 1.f / (1.f + __expf(-gate));
            float hn = o * tanhf(cS[b_own * CP + jbase + j_own]);
            tile[j_own * 17 + b_own] = hn;
            fred[b_own * 36 + j_own] = wf_s[jbase + j_own] * hn;
        }
        __syncthreads();
        // coalesced h_new + hs output (b-major)
        {
            int bo = tid >> 5, jq = tid & 31;
            float v = tile[jq * 17 + bo];
            g_h[nxt][(size_t)(bbase + bo) * NNH + jbase + jq] = v;
            out_hs[(size_t)(bbase + bo) * TT * NNH + (size_t)t * NNH + jbase + jq] = v;
        }
        if (tid < MB) {
            float s = 0.f;
            #pragma unroll
            for (int g4 = 0; g4 < 8; ++g4) {
                float4 v = *(const float4*)(fred + tid * 36 + 4 * g4);
                s += v.x + v.y + v.z + v.w;
            }
            g_fpart[ct * BB + bbase + tid] = s;
        }
        grp_arrive(barp);                         // #1: h_new + f partials visible

        // ================= PASS 2: P = A_t · c (hides barrier #1) =================
        uint64_t pacc[4][4];
        #pragma unroll
        for (int jj = 0; jj < 4; ++jj)
            #pragma unroll
            for (int bb = 0; bb < 4; ++bb) pacc[jj][bb] = 0;

        #pragma unroll
        for (int m = 0; m < 8; ++m) {
            float4 aN[4];
            if (m < 7) {
                #pragma unroll
                for (int jj = 0; jj < 4; ++jj)
                    aN[jj] = __ldg((const float4*)(Ar[jj] + 4 * (m + 1)));
            }
            ulonglong2 cv[4];
            #pragma unroll
            for (int bb = 0; bb < 4; ++bb)
                cv[bb] = *(const ulonglong2*)(cB[bb] + 4 * m);
            #pragma unroll
            for (int jj = 0; jj < 4; ++jj) {
                ulonglong2 av = *(const ulonglong2*)(&aC[jj]);
                #pragma unroll
                for (int bb = 0; bb < 4; ++bb) {
                    fma2(pacc[jj][bb], av.x, cv[bb].x);
                    fma2(pacc[jj][bb], av.y, cv[bb].y);
                }
            }
            if (m < 7) {
                #pragma unroll
                for (int jj = 0; jj < 4; ++jj) aC[jj] = aN[jj];
            }
        }

        // ====== P reduction (2 phases, reuse buffer) ======
        float psum = 0.f;
        #pragma unroll
        for (int jj = 0; jj < 2; ++jj)
            #pragma unroll
            for (int bb = 0; bb < 4; ++bb) {
                float2 v = unpack2(pacc[jj][bb]);
                red[((jt + 8 * jj) * 16 + (bt + 4 * bb)) * RP + kc] = v.x + v.y;
            }
        __syncthreads();
        if (tid < 256) {
            const float* rp = red + tid * RP;
            float4 r0 = *(const float4*)(rp + 0);
            float4 r1 = *(const float4*)(rp + 4);
            float4 r2 = *(const float4*)(rp + 8);
            float4 r3 = *(const float4*)(rp + 12);
            psum = (r0.x + r0.y + r0.z + r0.w) + (r1.x + r1.y + r1.z + r1.w)
                 + (r2.x + r2.y + r2.z + r2.w) + (r3.x + r3.y + r3.z + r3.w);
        }
        __syncthreads();
        #pragma unroll
        for (int jj = 2; jj < 4; ++jj)
            #pragma unroll
            for (int bb = 0; bb < 4; ++bb) {
                float2 v = unpack2(pacc[jj][bb]);
                red[((jt + 8 * (jj - 2)) * 16 + (bt + 4 * bb)) * RP + kc] = v.x + v.y;
            }
        __syncthreads();
        if (tid >= 256) {
            const float* rp = red + (tid - 256) * RP;
            float4 r0 = *(const float4*)(rp + 0);
            float4 r1 = *(const float4*)(rp + 4);
            float4 r2 = *(const float4*)(rp + 8);
            float4 r3 = *(const float4*)(rp + 12);
            psum = (r0.x + r0.y + r0.z + r0.w) + (r1.x + r1.y + r1.z + r1.w)
                 + (r2.x + r2.y + r2.z + r2.w) + (r3.x + r3.y + r3.z + r3.w);
        }

        grp_wait(barp, (unsigned)(2 * t + 1) * MB);   // group: h + f partials ready

        // stage h for next step via cp.async (no transpose needed)
        #pragma unroll
        for (int it = 0; it < 4; ++it) {
            int idx = tid + 512 * it;
            int b = idx >> 7, kq = idx & 127;
            cpa16(hS + b * CP + 4 * kq,
                  g_h[nxt] + (size_t)(bbase + b) * NNH + 4 * kq);
        }
        cpa_commit();

        if (tid < MB) {
            float s = 0.f;
            #pragma unroll
            for (int q = 0; q < NCOLT; ++q)
                s += __ldcg(&g_fpart[q * BB + bbase + tid]);
            f_s[tid] = bf0 + wf0 * xs[tid] + s;
        }
        __syncthreads();

        // ====== c_new (via tile for coalesced store) ======
        {
            float Bt = __ldg(&B_stack[t * NNH + jbase + j_own]);
            tile[j_own * 17 + b_own] = psum + f_s[b_own] * Bt;
        }
        __syncthreads();
        {
            int bo = tid >> 5, jq = tid & 31;
            float v = tile[jq * 17 + bo];
            g_c[nxt][(size_t)(bbase + bo) * NNH + jbase + jq] = v;
            if (t == TT - 1)
                out_cf[(size_t)(bbase + bo) * NNH + jbase + jq] = v;
        }
        grp_arrive(barp);                             // #2
        grp_wait(barp, (unsigned)(2 * t + 2) * MB);   // group: c_new ready

        // stage c for next step via cp.async
        #pragma unroll
        for (int it = 0; it < 4; ++it) {
            int idx = tid + 512 * it;
            int b = idx >> 7, kq = idx & 127;
            cpa16(cS + b * CP + 4 * kq,
                  g_c[nxt] + (size_t)(bbase + b) * NNH + 4 * kq);
        }
        cpa_commit();
        cpa_wait_all();
        __syncthreads();
    }
}

extern "C" void kernel_launch(void* const* d_in, const int* in_sizes, int n_in,
                              void* d_out, int out_size) {
    const float* x   = (const float*)d_in[0];
    const float* h0  = (const float*)d_in[1];
    const float* c0  = (const float*)d_in[2];
    const float* Wi  = (const float*)d_in[3];
    const float* bi  = (const float*)d_in[4];
    const float* Wh  = (const float*)d_in[5];
    const float* bh  = (const float*)d_in[6];
    const float* Wf  = (const float*)d_in[7];
    const float* bf  = (const float*)d_in[8];
    const float* A_s = (const float*)d_in[9];
    const float* B_s = (const float*)d_in[10];
    float* out = (float*)d_out;

    cudaFuncSetAttribute(hippo_persistent,
                         cudaFuncAttributeMaxDynamicSharedMemorySize, SM_BYTES);
    hippo_init<<<128, 256>>>(h0, c0);
    hippo_persistent<<<NCTA, NTHR, SM_BYTES>>>(x, Wi, bi, Wh, bh, Wf, bf,
                                               A_s, B_s, out);
}